// round 1
// baseline (speedup 1.0000x reference)
#include <cuda_runtime.h>
#include <cstdint>

#define EPS_F 1e-6f
#define S_DIM 2048
#define H_DIM 12
#define W_DIM 32
#define MAXSEG 33
#define PLANE ((size_t)S_DIM * S_DIM)

// -------- persistent scratch (device globals: no allocation allowed) --------
__device__ float g_A[S_DIM];        // log(|d|*c + 1 + eps), d = |i-j|
__device__ float g_invB[S_DIM];     // 1 / log(|c*pos_norm(i)| + 1 + eps)
__device__ float g_hinge[32];       // sorted ReLU hinge positions, padded +inf
__device__ float g_slope[MAXSEG * H_DIM];
__device__ float g_icpt [MAXSEG * H_DIM];

// ---------------------------------------------------------------------------
// Kernel 1: distance/normalizer tables (2048 entries each)
// ---------------------------------------------------------------------------
__global__ void fire_build_tables(const float* __restrict__ cp,
                                  const float* __restrict__ lmp,
                                  const float* __restrict__ ilp) {
    int t = blockIdx.x * blockDim.x + threadIdx.x;
    if (t >= S_DIM) return;
    float c   = cp[0];
    float thr = fabsf(lmp[0] * ilp[0]);
    // log_rel numerator table: abs_rel = |rel| + EPS, A = log(abs_rel*c + 1 + EPS)
    float abs_rel = (float)t + EPS_F;
    g_A[t] = logf((abs_rel * c + 1.0f) + EPS_F);
    // log_norm denominator table (per row i)
    float pos_norm = fmaxf((float)t, thr) + EPS_F;
    g_invB[t] = 1.0f / logf((fabsf(c * pos_norm) + 1.0f) + EPS_F);
}

// ---------------------------------------------------------------------------
// Kernel 2: piecewise-linear coefficients of the ReLU MLP in nd.
//   bias_h(nd) = slope[s][h]*nd + icpt[s][h] on segment s between sorted hinges.
//   Exact: ReLU(w1*nd+b1) is linear within a segment; active set fixed.
// 64 threads: t<32 rank-sorts hinges; t<nseg builds one segment's coeffs.
// ---------------------------------------------------------------------------
__global__ void fire_build_coeffs(const float* __restrict__ w1,
                                  const float* __restrict__ b1,
                                  const float* __restrict__ w2,
                                  const float* __restrict__ b2) {
    __shared__ float shW1[W_DIM], shB1[W_DIM], shT[W_DIM], shH[W_DIM + 1];
    __shared__ int shNh;
    const float INFF = __int_as_float(0x7f800000);
    int t = threadIdx.x;

    if (t < W_DIM) { shW1[t] = w1[t]; shB1[t] = b1[t]; }
    __syncthreads();
    if (t < W_DIM) {
        bool valid = (shW1[t] != 0.0f);           // w1==0 -> constant unit, no hinge
        shT[t] = valid ? (-shB1[t] / shW1[t]) : INFF;
    }
    __syncthreads();
    if (t < W_DIM) {
        float tv = shT[t];
        int rank = 0;
        #pragma unroll
        for (int v = 0; v < W_DIM; v++) {
            float o = shT[v];
            rank += (o < tv) || (o == tv && v < t);
        }
        shH[rank] = tv;
        if (t == 0) {
            int n = 0;
            for (int v = 0; v < W_DIM; v++) n += (shW1[v] != 0.0f);
            shNh = n;
        }
    }
    __syncthreads();
    int nh = shNh;
    if (t < 32) g_hinge[t] = (t < nh) ? shH[t] : INFF;   // pad with +inf

    int nseg = nh + 1;
    if (t < nseg) {
        // representative point strictly inside segment t
        float x;
        if (nh == 0)      x = 0.0f;
        else if (t == 0)  x = shH[0] - 1.0f;
        else if (t == nh) x = shH[nh - 1] + 1.0f;
        else              x = 0.5f * (shH[t - 1] + shH[t]);

        float sl[H_DIM], ic[H_DIM];
        #pragma unroll
        for (int h = 0; h < H_DIM; h++) { sl[h] = 0.0f; ic[h] = b2[h]; }
        for (int w = 0; w < W_DIM; w++) {
            float w1v = shW1[w], b1v = shB1[w];
            if (w1v * x + b1v > 0.0f) {             // unit active on this segment
                #pragma unroll
                for (int h = 0; h < H_DIM; h++) {
                    float w2v = w2[h * W_DIM + w];
                    sl[h] += w2v * w1v;
                    ic[h] += w2v * b1v;
                }
            }
        }
        #pragma unroll
        for (int h = 0; h < H_DIM; h++) {
            g_slope[t * H_DIM + h] = sl[h];
            g_icpt [t * H_DIM + h] = ic[h];
        }
    }
}

// ---------------------------------------------------------------------------
// Kernel 3: main fill. block = 256 threads, 4 consecutive j per thread
// (one float4 streaming store per head plane). blockIdx.y = row i,
// blockIdx.x selects which half of the row.
// ---------------------------------------------------------------------------
__global__ __launch_bounds__(256) void fire_main(float* __restrict__ out) {
    __shared__ float s_hinge[32];
    __shared__ float s_slope[MAXSEG * H_DIM];
    __shared__ float s_icpt [MAXSEG * H_DIM];

    int tid = threadIdx.x;
    for (int idx = tid; idx < MAXSEG * H_DIM; idx += 256) {
        s_slope[idx] = g_slope[idx];
        s_icpt [idx] = g_icpt [idx];
    }
    if (tid < 32) s_hinge[tid] = g_hinge[tid];
    __syncthreads();

    const int i  = blockIdx.y;
    const int j0 = blockIdx.x * 1024 + tid * 4;
    const float invB = g_invB[i];

    float nd[4];
    int   seg[4];
    #pragma unroll
    for (int k = 0; k < 4; k++) {
        int j = j0 + k;
        int d = abs(i - j);
        nd[k] = __ldg(&g_A[d]) * invB;
        // lower_bound over 32 (+inf padded) hinges: seg = #hinges <= nd
        int lo = 0, hi = 32;
        #pragma unroll
        for (int it = 0; it < 5; it++) {
            int mid = (lo + hi) >> 1;
            bool ge = (nd[k] >= s_hinge[mid]);
            lo = ge ? mid + 1 : lo;
            hi = ge ? hi : mid;
        }
        seg[k] = lo;
    }

    const size_t base = (size_t)i * S_DIM + j0;
    bool uni = (seg[0] == seg[1]) & (seg[1] == seg[2]) & (seg[2] == seg[3]);
    if (uni) {
        const float* sl = &s_slope[seg[0] * H_DIM];
        const float* ic = &s_icpt [seg[0] * H_DIM];
        #pragma unroll
        for (int h = 0; h < H_DIM; h++) {
            float s = sl[h], b = ic[h];
            float4 v;
            v.x = fmaf(nd[0], s, b);
            v.y = fmaf(nd[1], s, b);
            v.z = fmaf(nd[2], s, b);
            v.w = fmaf(nd[3], s, b);
            __stcs(reinterpret_cast<float4*>(out + (size_t)h * PLANE + base), v);
        }
    } else {
        #pragma unroll
        for (int h = 0; h < H_DIM; h++) {
            float4 v;
            v.x = fmaf(nd[0], s_slope[seg[0] * H_DIM + h], s_icpt[seg[0] * H_DIM + h]);
            v.y = fmaf(nd[1], s_slope[seg[1] * H_DIM + h], s_icpt[seg[1] * H_DIM + h]);
            v.z = fmaf(nd[2], s_slope[seg[2] * H_DIM + h], s_icpt[seg[2] * H_DIM + h]);
            v.w = fmaf(nd[3], s_slope[seg[3] * H_DIM + h], s_icpt[seg[3] * H_DIM + h]);
            __stcs(reinterpret_cast<float4*>(out + (size_t)h * PLANE + base), v);
        }
    }
}

// ---------------------------------------------------------------------------
// Inputs (metadata order): x, w1, b1, w2, b2, c, L_multiplier, init_L
// ---------------------------------------------------------------------------
extern "C" void kernel_launch(void* const* d_in, const int* in_sizes, int n_in,
                              void* d_out, int out_size) {
    const float* w1 = (const float*)d_in[1];
    const float* b1 = (const float*)d_in[2];
    const float* w2 = (const float*)d_in[3];
    const float* b2 = (const float*)d_in[4];
    const float* c  = (const float*)d_in[5];
    const float* lm = (const float*)d_in[6];
    const float* il = (const float*)d_in[7];
    float* out = (float*)d_out;

    fire_build_tables<<<(S_DIM + 255) / 256, 256>>>(c, lm, il);
    fire_build_coeffs<<<1, 64>>>(w1, b1, w2, b2);

    dim3 grid(S_DIM / 1024, S_DIM);   // (2, 2048)
    fire_main<<<grid, 256>>>(out);
}

// round 3
// speedup vs baseline: 1.0147x; 1.0147x over previous
#include <cuda_runtime.h>
#include <cstdint>

#define EPS_F 1e-6f
#define S_DIM 2048
#define H_DIM 12
#define W_DIM 32
#define MAXSEG 33
#define PLANE ((size_t)S_DIM * S_DIM)

// -------- persistent scratch (device globals: no allocation allowed) --------
__device__ float g_A[S_DIM];        // log(|d|*c + 1 + eps), d = |i-j|
__device__ float g_invB[S_DIM];     // 1 / log(|c*pos_norm(i)| + 1 + eps)
__device__ float g_hinge[32];       // sorted ReLU hinge positions, padded +inf
__device__ float g_slope[MAXSEG * H_DIM];
__device__ float g_icpt [MAXSEG * H_DIM];

// ---------------------------------------------------------------------------
// Fused setup kernel (one block, 1024 threads):
//  * threads t: table entries t and t+1024 (g_A, g_invB)
//  * warp 0:   rank-sort of ReLU hinge positions
//  * t<33:     per-segment slope/intercept of the exact piecewise-linear MLP
// ---------------------------------------------------------------------------
__global__ __launch_bounds__(1024) void fire_setup(const float* __restrict__ w1,
                                                   const float* __restrict__ b1,
                                                   const float* __restrict__ w2,
                                                   const float* __restrict__ b2,
                                                   const float* __restrict__ cp,
                                                   const float* __restrict__ lmp,
                                                   const float* __restrict__ ilp) {
    __shared__ float shW1[W_DIM], shB1[W_DIM], shT[W_DIM], shH[W_DIM + 1];
    __shared__ int shNh;
    const float INFF = __int_as_float(0x7f800000);
    const int t = threadIdx.x;

    const float c   = cp[0];
    const float thr = fabsf(lmp[0] * ilp[0]);

    // ---- tables: 2 entries per thread ----
    #pragma unroll
    for (int r = 0; r < 2; r++) {
        int e = t + r * 1024;
        float abs_rel = (float)e + EPS_F;
        g_A[e] = logf((abs_rel * c + 1.0f) + EPS_F);
        float pos_norm = fmaxf((float)e, thr) + EPS_F;
        g_invB[e] = 1.0f / logf((fabsf(c * pos_norm) + 1.0f) + EPS_F);
    }

    // ---- hinge computation + sort (warp 0) ----
    if (t < W_DIM) { shW1[t] = w1[t]; shB1[t] = b1[t]; }
    __syncthreads();
    if (t < W_DIM) {
        bool valid = (shW1[t] != 0.0f);           // w1==0 -> no hinge
        shT[t] = valid ? (-shB1[t] / shW1[t]) : INFF;
    }
    __syncthreads();
    if (t < W_DIM) {
        float tv = shT[t];
        int rank = 0;
        #pragma unroll
        for (int v = 0; v < W_DIM; v++) {
            float o = shT[v];
            rank += (o < tv) || (o == tv && v < t);
        }
        shH[rank] = tv;
        if (t == 0) {
            int n = 0;
            for (int v = 0; v < W_DIM; v++) n += (shW1[v] != 0.0f);
            shNh = n;
        }
    }
    __syncthreads();
    const int nh = shNh;
    if (t < 32) g_hinge[t] = (t < nh) ? shH[t] : INFF;   // pad with +inf

    // ---- per-segment coefficients ----
    if (t < nh + 1) {
        float x;                                   // interior point of segment t
        if (nh == 0)      x = 0.0f;
        else if (t == 0)  x = shH[0] - 1.0f;
        else if (t == nh) x = shH[nh - 1] + 1.0f;
        else              x = 0.5f * (shH[t - 1] + shH[t]);

        float sl[H_DIM], ic[H_DIM];
        #pragma unroll
        for (int h = 0; h < H_DIM; h++) { sl[h] = 0.0f; ic[h] = b2[h]; }
        for (int w = 0; w < W_DIM; w++) {
            float w1v = shW1[w], b1v = shB1[w];
            if (w1v * x + b1v > 0.0f) {            // unit active on this segment
                #pragma unroll
                for (int h = 0; h < H_DIM; h++) {
                    float w2v = w2[h * W_DIM + w];
                    sl[h] += w2v * w1v;
                    ic[h] += w2v * b1v;
                }
            }
        }
        #pragma unroll
        for (int h = 0; h < H_DIM; h++) {
            g_slope[t * H_DIM + h] = sl[h];
            g_icpt [t * H_DIM + h] = ic[h];
        }
    }
}

// ---------------------------------------------------------------------------
// Main fill: block = 256 threads, 4 consecutive j per thread (one float4
// streaming store per head plane). blockIdx.y = row i, blockIdx.x = row half.
// ---------------------------------------------------------------------------
__global__ __launch_bounds__(256) void fire_main(float* __restrict__ out) {
    __shared__ float s_hinge[32];
    __shared__ float s_slope[MAXSEG * H_DIM];
    __shared__ float s_icpt [MAXSEG * H_DIM];

    int tid = threadIdx.x;
    for (int idx = tid; idx < MAXSEG * H_DIM; idx += 256) {
        s_slope[idx] = g_slope[idx];
        s_icpt [idx] = g_icpt [idx];
    }
    if (tid < 32) s_hinge[tid] = g_hinge[tid];
    __syncthreads();

    const int i  = blockIdx.y;
    const int j0 = blockIdx.x * 1024 + tid * 4;
    const float invB = g_invB[i];

    float nd[4];
    int   seg[4];
    #pragma unroll
    for (int k = 0; k < 4; k++) {
        int j = j0 + k;
        int d = abs(i - j);
        nd[k] = __ldg(&g_A[d]) * invB;
        // lower_bound over 32 (+inf padded) hinges: seg = #hinges <= nd
        int lo = 0, hi = 32;
        #pragma unroll
        for (int it = 0; it < 5; it++) {
            int mid = (lo + hi) >> 1;
            bool ge = (nd[k] >= s_hinge[mid]);
            lo = ge ? mid + 1 : lo;
            hi = ge ? hi : mid;
        }
        seg[k] = lo;
    }

    const size_t base = (size_t)i * S_DIM + j0;
    bool uni = (seg[0] == seg[1]) & (seg[1] == seg[2]) & (seg[2] == seg[3]);
    if (uni) {
        const float* sl = &s_slope[seg[0] * H_DIM];
        const float* ic = &s_icpt [seg[0] * H_DIM];
        #pragma unroll
        for (int h = 0; h < H_DIM; h++) {
            float s = sl[h], b = ic[h];
            float4 v;
            v.x = fmaf(nd[0], s, b);
            v.y = fmaf(nd[1], s, b);
            v.z = fmaf(nd[2], s, b);
            v.w = fmaf(nd[3], s, b);
            __stcs(reinterpret_cast<float4*>(out + (size_t)h * PLANE + base), v);
        }
    } else {
        #pragma unroll
        for (int h = 0; h < H_DIM; h++) {
            float4 v;
            v.x = fmaf(nd[0], s_slope[seg[0] * H_DIM + h], s_icpt[seg[0] * H_DIM + h]);
            v.y = fmaf(nd[1], s_slope[seg[1] * H_DIM + h], s_icpt[seg[1] * H_DIM + h]);
            v.z = fmaf(nd[2], s_slope[seg[2] * H_DIM + h], s_icpt[seg[2] * H_DIM + h]);
            v.w = fmaf(nd[3], s_slope[seg[3] * H_DIM + h], s_icpt[seg[3] * H_DIM + h]);
            __stcs(reinterpret_cast<float4*>(out + (size_t)h * PLANE + base), v);
        }
    }
}

// ---------------------------------------------------------------------------
// Inputs (metadata order): x, w1, b1, w2, b2, c, L_multiplier, init_L
// ---------------------------------------------------------------------------
extern "C" void kernel_launch(void* const* d_in, const int* in_sizes, int n_in,
                              void* d_out, int out_size) {
    const float* w1 = (const float*)d_in[1];
    const float* b1 = (const float*)d_in[2];
    const float* w2 = (const float*)d_in[3];
    const float* b2 = (const float*)d_in[4];
    const float* c  = (const float*)d_in[5];
    const float* lm = (const float*)d_in[6];
    const float* il = (const float*)d_in[7];
    float* out = (float*)d_out;

    fire_setup<<<1, 1024>>>(w1, b1, w2, b2, c, lm, il);

    dim3 grid(S_DIM / 1024, S_DIM);   // (2, 2048)
    fire_main<<<grid, 256>>>(out);
}

// round 4
// speedup vs baseline: 1.0186x; 1.0039x over previous
#include <cuda_runtime.h>
#include <cstdint>

#define EPS_F 1e-6f
#define S_DIM 2048
#define H_DIM 12
#define W_DIM 32
#define MAXSEG 33
#define PLANE ((size_t)S_DIM * S_DIM)

#define NBLOCKS 444   // 3 CTAs/SM * 148 SMs
#define NTHREADS 512  // one full row (512 * 4 j) per iteration

// ---------------------------------------------------------------------------
// Single fused persistent kernel.
// Phase 1 (per block, in smem): A-table, hinge sort, piecewise-linear coeffs.
// Phase 2: grid-stride over rows i; 512 threads x 4 j = 2048 j per row;
//          12 float4 streaming stores per thread (one per head plane).
// ---------------------------------------------------------------------------
__global__ __launch_bounds__(NTHREADS) void fire_all(
        const float* __restrict__ w1,
        const float* __restrict__ b1,
        const float* __restrict__ w2,
        const float* __restrict__ b2,
        const float* __restrict__ cp,
        const float* __restrict__ lmp,
        const float* __restrict__ ilp,
        float* __restrict__ out) {
    __shared__ float sA[S_DIM];                 // log(|d|*c + 1 + eps)
    __shared__ float s_hinge[32];
    __shared__ float s_slope[MAXSEG * H_DIM];
    __shared__ float s_icpt [MAXSEG * H_DIM];
    __shared__ float shW1[W_DIM], shB1[W_DIM], shT[W_DIM], shH[W_DIM + 1];
    __shared__ int   shNh;

    const float INFF = __int_as_float(0x7f800000);
    const int t = threadIdx.x;

    const float c   = __ldg(cp);
    const float thr = fabsf(__ldg(lmp) * __ldg(ilp));

    // ---- A table: 4 entries per thread ----
    #pragma unroll
    for (int r = 0; r < S_DIM / NTHREADS; r++) {
        int e = t + r * NTHREADS;
        float abs_rel = (float)e + EPS_F;
        sA[e] = logf((abs_rel * c + 1.0f) + EPS_F);
    }

    // ---- hinge computation + rank sort (warp 0 scope data, parallel build) --
    if (t < W_DIM) { shW1[t] = w1[t]; shB1[t] = b1[t]; }
    __syncthreads();
    if (t < W_DIM) {
        bool valid = (shW1[t] != 0.0f);            // w1==0 -> no hinge
        shT[t] = valid ? (-shB1[t] / shW1[t]) : INFF;
    }
    __syncthreads();
    if (t < W_DIM) {
        float tv = shT[t];
        int rank = 0;
        #pragma unroll
        for (int v = 0; v < W_DIM; v++) {
            float o = shT[v];
            rank += (o < tv) || (o == tv && v < t);
        }
        shH[rank] = tv;
        if (t == 0) {
            int n = 0;
            for (int v = 0; v < W_DIM; v++) n += (shW1[v] != 0.0f);
            shNh = n;
        }
    }
    __syncthreads();
    const int nh = shNh;
    if (t < 32) s_hinge[t] = (t < nh) ? shH[t] : INFF;   // +inf padded

    // ---- coefficients: one (segment, head) pair per thread ----
    if (t < (nh + 1) * H_DIM) {
        int s = t / H_DIM;
        int h = t - s * H_DIM;
        float x;                                    // interior point of segment s
        if (nh == 0)      x = 0.0f;
        else if (s == 0)  x = shH[0] - 1.0f;
        else if (s == nh) x = shH[nh - 1] + 1.0f;
        else              x = 0.5f * (shH[s - 1] + shH[s]);

        float sl = 0.0f, ic = __ldg(&b2[h]);
        #pragma unroll
        for (int w = 0; w < W_DIM; w++) {
            float w1v = shW1[w], b1v = shB1[w];
            if (w1v * x + b1v > 0.0f) {             // unit active on this segment
                float w2v = __ldg(&w2[h * W_DIM + w]);
                sl = fmaf(w2v, w1v, sl);
                ic = fmaf(w2v, b1v, ic);
            }
        }
        s_slope[t] = sl;
        s_icpt [t] = ic;
    }
    __syncthreads();

    // ---- main fill: grid-stride over rows ----
    const int j0 = t * 4;
    for (int i = blockIdx.x; i < S_DIM; i += gridDim.x) {
        float pos_norm = fmaxf((float)i, thr) + EPS_F;
        float invB = 1.0f / logf((fabsf(c * pos_norm) + 1.0f) + EPS_F);

        float nd[4];
        int   seg[4];
        #pragma unroll
        for (int k = 0; k < 4; k++) {
            int d = abs(i - (j0 + k));
            nd[k] = sA[d] * invB;
            // lower_bound over 32 (+inf padded) hinges
            int lo = 0, hi = 32;
            #pragma unroll
            for (int it = 0; it < 5; it++) {
                int mid = (lo + hi) >> 1;
                bool ge = (nd[k] >= s_hinge[mid]);
                lo = ge ? mid + 1 : lo;
                hi = ge ? hi : mid;
            }
            seg[k] = lo;
        }

        const size_t base = (size_t)i * S_DIM + j0;
        bool uni = (seg[0] == seg[1]) & (seg[1] == seg[2]) & (seg[2] == seg[3]);
        if (uni) {
            const float* sl = &s_slope[seg[0] * H_DIM];
            const float* ic = &s_icpt [seg[0] * H_DIM];
            #pragma unroll
            for (int h = 0; h < H_DIM; h++) {
                float s = sl[h], b = ic[h];
                float4 v;
                v.x = fmaf(nd[0], s, b);
                v.y = fmaf(nd[1], s, b);
                v.z = fmaf(nd[2], s, b);
                v.w = fmaf(nd[3], s, b);
                __stcs(reinterpret_cast<float4*>(out + (size_t)h * PLANE + base), v);
            }
        } else {
            #pragma unroll
            for (int h = 0; h < H_DIM; h++) {
                float4 v;
                v.x = fmaf(nd[0], s_slope[seg[0] * H_DIM + h], s_icpt[seg[0] * H_DIM + h]);
                v.y = fmaf(nd[1], s_slope[seg[1] * H_DIM + h], s_icpt[seg[1] * H_DIM + h]);
                v.z = fmaf(nd[2], s_slope[seg[2] * H_DIM + h], s_icpt[seg[2] * H_DIM + h]);
                v.w = fmaf(nd[3], s_slope[seg[3] * H_DIM + h], s_icpt[seg[3] * H_DIM + h]);
                __stcs(reinterpret_cast<float4*>(out + (size_t)h * PLANE + base), v);
            }
        }
    }
}

// ---------------------------------------------------------------------------
// Inputs (metadata order): x, w1, b1, w2, b2, c, L_multiplier, init_L
// ---------------------------------------------------------------------------
extern "C" void kernel_launch(void* const* d_in, const int* in_sizes, int n_in,
                              void* d_out, int out_size) {
    const float* w1 = (const float*)d_in[1];
    const float* b1 = (const float*)d_in[2];
    const float* w2 = (const float*)d_in[3];
    const float* b2 = (const float*)d_in[4];
    const float* c  = (const float*)d_in[5];
    const float* lm = (const float*)d_in[6];
    const float* il = (const float*)d_in[7];
    float* out = (float*)d_out;

    fire_all<<<NBLOCKS, NTHREADS>>>(w1, b1, w2, b2, c, lm, il, out);
}